// round 11
// baseline (speedup 1.0000x reference)
#include <cuda_runtime.h>

// Problem constants
#define NPTS     8193            // positions per chain (incl. leading zero row)
#define NCHAIN   2
#define CONFLEN  16388

// Chunking: 32-point tiles, one warp per tile pair
#define CHUNK    32
#define NCHUNK   257                             // ceil(8193/32)
#define PADN     (NCHUNK * CHUNK)                // 8224
#define NPAIR    (NCHUNK * (NCHUNK + 1) / 2)     // 33153 (cj >= ci)
#define MAXITEMS (NPAIR * NCHAIN)

#define SBLOCK   1024                            // setup block
#define PBLOCK   256                             // pair block
#define PGRID    592                             // pair grid
#define NWARPS   (PGRID * (PBLOCK / 32))         // 4736

// Scaled-space cutoff: dropped pair value <= 2^(-0.5*64) = 2.3e-10
#define DCUT_HAT 8.0f

// Fixed-point scale for deterministic integer accumulation
#define FXSCALE  16777216.0f     // 2^24

// Scratch (no allocations allowed; zero-initialized at load)
__device__ float4 g_pts[NCHAIN][PADN];           // (x_hat, y_hat, z_hat, a)
__device__ int    g_live[MAXITEMS];              // packed live items
__device__ unsigned int g_live_cnt;
__device__ unsigned long long g_acc;             // fixed-point sum
__device__ unsigned int g_count;                 // finished-block counter

// ---------------------------------------------------------------------------
// Setup + plan: one block per chain. Register-resident 8-steps-per-thread
// prefix sum, scaled points, 32-point chunk bounds, then cull all tile pairs
// into a compact live list with WARP-AGGREGATED atomics (1 atomic/warp/iter).
// ---------------------------------------------------------------------------
__global__ void __launch_bounds__(SBLOCK)
setup_kernel(const float* __restrict__ conf) {
    const int chain = blockIdx.x;
    const int tid = threadIdx.x;
    const int lane = tid & 31, warp = tid >> 5;
    const float2* cp = (const float2*)(conf + chain * CONFLEN + 4);
    const float TWO_PI = 6.2831853071795864769f;

    float px[8], py[8], pz[8];
    float sx = 0.f, sy = 0.f, sz = 0.f;
    #pragma unroll
    for (int m = 0; m < 8; m++) {
        float2 rr = cp[tid * 8 + m];
        float r1 = rr.x + 0.5f;
        float r2 = rr.y + 0.5f;
        float z  = 1.0f - 2.0f * r2;                   // cos(theta)
        float sth = sqrtf(fmaxf(1.0f - z * z, 0.0f));  // sin(theta)
        float s, c;
        __sincosf(r1 * TWO_PI, &s, &c);
        sx += sth * c;
        sy += sth * s;
        sz += z;
        px[m] = sx; py[m] = sy; pz[m] = sz;
    }

    // warp inclusive scan of thread totals
    float tx = sx, ty = sy, tz = sz;
    #pragma unroll
    for (int d = 1; d < 32; d <<= 1) {
        float ox = __shfl_up_sync(0xffffffffu, tx, d);
        float oy = __shfl_up_sync(0xffffffffu, ty, d);
        float oz = __shfl_up_sync(0xffffffffu, tz, d);
        if (lane >= d) { tx += ox; ty += oy; tz += oz; }
    }

    __shared__ float3 wtot[32], woff[32];
    __shared__ float4 lastpt_s;
    __shared__ float4 cb[NCHUNK];
    if (lane == 31) wtot[warp] = make_float3(tx, ty, tz);
    __syncthreads();
    if (tid == 0) {
        float ax = 0.f, ay = 0.f, az = 0.f;
        #pragma unroll
        for (int w = 0; w < 32; w++) {
            float3 v = wtot[w];
            woff[w] = make_float3(ax, ay, az);
            ax += v.x; ay += v.y; az += v.z;
        }
    }
    __syncthreads();
    float bx = woff[warp].x + (tx - sx);
    float by = woff[warp].y + (ty - sy);
    float bz = woff[warp].z + (tz - sz);

    // arg = a_i + a_j + dot(p_hat_i, p_hat_j), p_hat = SS*p, a=-0.5|p_hat|^2
    const float S2 = 8.0f * 1.4426950408889634f;   // 8*log2(e)
    const float SS = sqrtf(S2);                    // scaled step length

    float4 mylast = make_float4(0.f, 0.f, 0.f, 0.f);
    float mnx = 1e30f, mxx = -1e30f, mny = 1e30f, mxy = -1e30f;
    float mnz = 1e30f, mxz = -1e30f;
    #pragma unroll
    for (int m = 0; m < 8; m++) {
        float xh = SS * (bx + px[m]);
        float yh = SS * (by + py[m]);
        float zh = SS * (bz + pz[m]);
        float a = -0.5f * (xh * xh + yh * yh + zh * zh);
        mylast = make_float4(xh, yh, zh, a);
        g_pts[chain][tid * 8 + m + 1] = mylast;
        mnx = fminf(mnx, xh); mxx = fmaxf(mxx, xh);
        mny = fminf(mny, yh); mxy = fmaxf(mxy, yh);
        mnz = fminf(mnz, zh); mxz = fmaxf(mxz, zh);
    }
    if (tid == 0)    g_pts[chain][0] = make_float4(0.f, 0.f, 0.f, 0.f);
    if (tid == 1023) lastpt_s = mylast;   // point 8192

    // chunk bounds: threads 4c..4c+3 cover points [32c+1, 32c+33);
    // +SS inflation covers boundary point 32c.
    #pragma unroll
    for (int d = 1; d < 4; d <<= 1) {
        mnx = fminf(mnx, __shfl_xor_sync(0xffffffffu, mnx, d, 4));
        mxx = fmaxf(mxx, __shfl_xor_sync(0xffffffffu, mxx, d, 4));
        mny = fminf(mny, __shfl_xor_sync(0xffffffffu, mny, d, 4));
        mxy = fmaxf(mxy, __shfl_xor_sync(0xffffffffu, mxy, d, 4));
        mnz = fminf(mnz, __shfl_xor_sync(0xffffffffu, mnz, d, 4));
        mxz = fmaxf(mxz, __shfl_xor_sync(0xffffffffu, mxz, d, 4));
    }
    if ((tid & 3) == 0) {
        float hx = 0.5f * (mxx - mnx);
        float hy = 0.5f * (mxy - mny);
        float hz = 0.5f * (mxz - mnz);
        float r = sqrtf(hx * hx + hy * hy + hz * hz) + SS + 1e-2f;
        cb[tid >> 2] = make_float4(0.5f * (mnx + mxx), 0.5f * (mny + mxy),
                                   0.5f * (mnz + mxz), r);
    }
    __syncthreads();
    // chunk 256 = real point 8192 + 31 pads, all at lastpt
    if (tid == 0)
        cb[256] = make_float4(lastpt_s.x, lastpt_s.y, lastpt_s.z, 0.05f);
    // pads: a=-1e30 -> exp2 underflows to exactly 0
    if (tid < PADN - NPTS)
        g_pts[chain][NPTS + tid] =
            make_float4(lastpt_s.x, lastpt_s.y, lastpt_s.z, -1e30f);
    __syncthreads();

    // ---- plan: contiguous pair range per thread, warp-aggregated emit ----
    const int per = (NPAIR + SBLOCK - 1) / SBLOCK;       // 33 (warp-uniform)
    int p0 = tid * per;

    // decode start index -> (ci, cj); S(ci) = ci*(2*NCHUNK+1-ci)/2
    int pd = min(p0, NPAIR - 1);
    float disc = (float)((2 * NCHUNK + 1) * (2 * NCHUNK + 1)) - 8.0f * (float)pd;
    int ci = (int)(((float)(2 * NCHUNK + 1) - sqrtf(disc)) * 0.5f);
    if (ci > NCHUNK - 1) ci = NCHUNK - 1;
    if (ci < 0) ci = 0;
    while (ci > 0 && (ci * (2 * NCHUNK + 1 - ci)) / 2 > pd) ci--;
    while (((ci + 1) * (2 * NCHUNK + 1 - (ci + 1))) / 2 <= pd) ci++;
    int cj = ci + (pd - (ci * (2 * NCHUNK + 1 - ci)) / 2);

    for (int k = 0; k < per; k++) {                      // lockstep trip count
        int p = p0 + k;
        bool pred = false;
        if (p < NPAIR) {
            float4 bi = cb[ci];
            float4 bj = cb[cj];
            float dx = bi.x - bj.x, dy = bi.y - bj.y, dz = bi.z - bj.z;
            float rr = bi.w + bj.w + DCUT_HAT;
            pred = (dx * dx + dy * dy + dz * dz <= rr * rr);
        }
        unsigned int mask = __ballot_sync(0xffffffffu, pred);
        if (mask) {
            int cnt = __popc(mask);
            unsigned int base;
            if (lane == 0) base = atomicAdd(&g_live_cnt, (unsigned int)cnt);
            base = __shfl_sync(0xffffffffu, base, 0);
            if (pred) {
                unsigned int off = base + __popc(mask & ((1u << lane) - 1u));
                g_live[off] = (chain << 20) | (ci << 10) | cj;
            }
        }
        if (p < NPAIR) { if (++cj >= NCHUNK) { ci++; cj = ci; } }
    }
}

// ---------------------------------------------------------------------------
// Pair kernel: one warp per live tile pair (grid-stride), no block sync in
// the loop. 4 independent FMA/ex2/acc chains for ILP. Per-item fixed-point
// quantization -> order-independent sum. Last block finalizes + resets.
// ---------------------------------------------------------------------------
__global__ void __launch_bounds__(PBLOCK)
pair_kernel(float* __restrict__ out) {
    const int tid = threadIdx.x;
    const int lane = tid & 31;
    const unsigned int gw = blockIdx.x * (PBLOCK / 32) + (tid >> 5);

    const unsigned int nitems = g_live_cnt;
    unsigned long long ll = 0ULL;

    for (unsigned int it = gw; it < nitems; it += NWARPS) {
        const int item = g_live[it];
        const int chain = item >> 20;
        const int ci = (item >> 10) & 1023;
        const int cj = item & 1023;

        const float4* __restrict__ jp = &g_pts[chain][cj * CHUNK];
        float4 ip = g_pts[chain][ci * CHUNK + lane];
        float a0 = 0.f, a1 = 0.f, a2 = 0.f, a3 = 0.f;

        if (ci != cj) {
            #pragma unroll
            for (int jj = 0; jj < CHUNK; jj += 4) {
                float4 q0 = __ldg(&jp[jj]);
                float4 q1 = __ldg(&jp[jj + 1]);
                float4 q2 = __ldg(&jp[jj + 2]);
                float4 q3 = __ldg(&jp[jj + 3]);
                float m0 = fmaf(ip.x, q0.x, q0.w);
                float m1 = fmaf(ip.x, q1.x, q1.w);
                float m2 = fmaf(ip.x, q2.x, q2.w);
                float m3 = fmaf(ip.x, q3.x, q3.w);
                m0 = fmaf(ip.y, q0.y, m0);
                m1 = fmaf(ip.y, q1.y, m1);
                m2 = fmaf(ip.y, q2.y, m2);
                m3 = fmaf(ip.y, q3.y, m3);
                m0 = fmaf(ip.z, q0.z, m0);
                m1 = fmaf(ip.z, q1.z, m1);
                m2 = fmaf(ip.z, q2.z, m2);
                m3 = fmaf(ip.z, q3.z, m3);
                float e0, e1, e2, e3;
                asm("ex2.approx.f32 %0, %1;" : "=f"(e0) : "f"(m0 + ip.w));
                asm("ex2.approx.f32 %0, %1;" : "=f"(e1) : "f"(m1 + ip.w));
                asm("ex2.approx.f32 %0, %1;" : "=f"(e2) : "f"(m2 + ip.w));
                asm("ex2.approx.f32 %0, %1;" : "=f"(e3) : "f"(m3 + ip.w));
                a0 += e0; a1 += e1; a2 += e2; a3 += e3;
            }
        } else {
            #pragma unroll
            for (int jj = 0; jj < CHUNK; jj += 4) {
                float4 q0 = __ldg(&jp[jj]);
                float4 q1 = __ldg(&jp[jj + 1]);
                float4 q2 = __ldg(&jp[jj + 2]);
                float4 q3 = __ldg(&jp[jj + 3]);
                float m0 = fmaf(ip.x, q0.x, q0.w);
                float m1 = fmaf(ip.x, q1.x, q1.w);
                float m2 = fmaf(ip.x, q2.x, q2.w);
                float m3 = fmaf(ip.x, q3.x, q3.w);
                m0 = fmaf(ip.y, q0.y, m0);
                m1 = fmaf(ip.y, q1.y, m1);
                m2 = fmaf(ip.y, q2.y, m2);
                m3 = fmaf(ip.y, q3.y, m3);
                m0 = fmaf(ip.z, q0.z, m0);
                m1 = fmaf(ip.z, q1.z, m1);
                m2 = fmaf(ip.z, q2.z, m2);
                m3 = fmaf(ip.z, q3.z, m3);
                float e0, e1, e2, e3;
                asm("ex2.approx.f32 %0, %1;" : "=f"(e0) : "f"(m0 + ip.w));
                asm("ex2.approx.f32 %0, %1;" : "=f"(e1) : "f"(m1 + ip.w));
                asm("ex2.approx.f32 %0, %1;" : "=f"(e2) : "f"(m2 + ip.w));
                asm("ex2.approx.f32 %0, %1;" : "=f"(e3) : "f"(m3 + ip.w));
                a0 += (jj     > lane) ? e0 : 0.f;    // strict upper triangle
                a1 += (jj + 1 > lane) ? e1 : 0.f;
                a2 += (jj + 2 > lane) ? e2 : 0.f;
                a3 += (jj + 3 > lane) ? e3 : 0.f;
            }
        }

        float acc = (a0 + a1) + (a2 + a3);
        #pragma unroll
        for (int d = 16; d > 0; d >>= 1)
            acc += __shfl_down_sync(0xffffffffu, acc, d);
        if (lane == 0)
            ll += (unsigned long long)__float2ll_rn(acc * FXSCALE);
    }

    if (lane == 0 && ll) atomicAdd(&g_acc, ll);
    __threadfence();
    __syncthreads();

    if (tid == 0) {
        unsigned int done = atomicAdd(&g_count, 1u);
        if (done == PGRID - 1) {
            unsigned long long raw = atomicAdd(&g_acc, 0ULL);
            double sum = (double)(long long)raw * (1.0 / (double)FXSCALE);
            out[0] = (float)(10.0 * (2.0 * sum + (double)(NCHAIN * NPTS)));
            // reset for next graph replay (all blocks are past all reads)
            atomicExch(&g_acc, 0ULL);
            atomicExch(&g_count, 0u);
            atomicExch(&g_live_cnt, 0u);
        }
    }
}

extern "C" void kernel_launch(void* const* d_in, const int* in_sizes, int n_in,
                              void* d_out, int out_size) {
    const float* conf = (const float*)d_in[0];
    float* out = (float*)d_out;

    setup_kernel<<<NCHAIN, SBLOCK>>>(conf);
    pair_kernel<<<PGRID, PBLOCK>>>(out);
}

// round 12
// speedup vs baseline: 1.0547x; 1.0547x over previous
#include <cuda_runtime.h>

// Problem constants
#define NPTS     8193            // positions per chain (incl. leading zero row)
#define NCHAIN   2
#define CONFLEN  16388

// Two-level chunking: 128-point chunks (coarse, per block), 32-point subchunks
#define NT       68                              // 128-point chunks
#define PADN     (NT * 128)                      // 8704
#define NSUB     (NT * 4)                        // 272 32-point subchunks
#define NP       (NT * (NT + 1) / 2)             // 2346 chunk pairs (tj >= ti)
#define NB       (NP * NCHAIN)                   // 4692 blocks

#define PBLOCK   128

// Scaled-space cutoff: dropped pair value <= 2^(-0.5*64) = 2.3e-10
#define DCUT_HAT 8.0f

// Fixed-point scale for deterministic integer accumulation
#define FXSCALE  16777216.0f     // 2^24

// Scratch (no allocations allowed; zero-initialized at load)
__device__ float4 g_pts[NCHAIN][PADN];           // (x_hat, y_hat, z_hat, a)
__device__ float4 g_cb[NCHAIN][NT];              // coarse bounds (cx,cy,cz,r)
__device__ float4 g_cb32[NCHAIN][NSUB];          // fine bounds
__device__ unsigned long long g_acc;             // fixed-point sum
__device__ unsigned int g_count;                 // finished-block counter

// ---------------------------------------------------------------------------
// Setup: one block (1024 threads) per chain, 8 steps per thread (register-
// resident, R4-proven). Emits scaled points + pads + two-level chunk bounds.
// ---------------------------------------------------------------------------
__global__ void __launch_bounds__(1024)
setup_kernel(const float* __restrict__ conf) {
    const int chain = blockIdx.x;
    const int t = threadIdx.x;
    const int lane = t & 31, warp = t >> 5;
    const float2* cp = (const float2*)(conf + chain * CONFLEN + 4);
    const float TWO_PI = 6.2831853071795864769f;

    float px[8], py[8], pz[8];
    float sx = 0.f, sy = 0.f, sz = 0.f;
    #pragma unroll
    for (int m = 0; m < 8; m++) {
        float2 rr = cp[t * 8 + m];
        float r1 = rr.x + 0.5f;
        float r2 = rr.y + 0.5f;
        float z  = 1.0f - 2.0f * r2;                   // cos(theta)
        float sth = sqrtf(fmaxf(1.0f - z * z, 0.0f));  // sin(theta)
        float s, c;
        __sincosf(r1 * TWO_PI, &s, &c);
        sx += sth * c;
        sy += sth * s;
        sz += z;
        px[m] = sx; py[m] = sy; pz[m] = sz;
    }

    // warp inclusive scan of thread totals
    float tx = sx, ty = sy, tz = sz;
    #pragma unroll
    for (int d = 1; d < 32; d <<= 1) {
        float ox = __shfl_up_sync(0xffffffffu, tx, d);
        float oy = __shfl_up_sync(0xffffffffu, ty, d);
        float oz = __shfl_up_sync(0xffffffffu, tz, d);
        if (lane >= d) { tx += ox; ty += oy; tz += oz; }
    }

    __shared__ float3 wtot[32], woff[32];
    __shared__ float4 lastpt_s;
    if (lane == 31) wtot[warp] = make_float3(tx, ty, tz);
    __syncthreads();
    if (t == 0) {
        float ax = 0.f, ay = 0.f, az = 0.f;
        #pragma unroll
        for (int w = 0; w < 32; w++) {
            float3 v = wtot[w];
            woff[w] = make_float3(ax, ay, az);
            ax += v.x; ay += v.y; az += v.z;
        }
    }
    __syncthreads();
    float bx = woff[warp].x + (tx - sx);
    float by = woff[warp].y + (ty - sy);
    float bz = woff[warp].z + (tz - sz);

    // arg = a_i + a_j + dot(p_hat_i, p_hat_j), p_hat = SS*p, a=-0.5|p_hat|^2
    const float S2 = 8.0f * 1.4426950408889634f;   // 8*log2(e)
    const float SS = sqrtf(S2);                    // scaled step length

    float4 mylast = make_float4(0.f, 0.f, 0.f, 0.f);
    float mnx = 1e30f, mxx = -1e30f, mny = 1e30f, mxy = -1e30f;
    float mnz = 1e30f, mxz = -1e30f;
    #pragma unroll
    for (int m = 0; m < 8; m++) {
        float xh = SS * (bx + px[m]);
        float yh = SS * (by + py[m]);
        float zh = SS * (bz + pz[m]);
        float a = -0.5f * (xh * xh + yh * yh + zh * zh);
        mylast = make_float4(xh, yh, zh, a);
        g_pts[chain][t * 8 + m + 1] = mylast;
        mnx = fminf(mnx, xh); mxx = fmaxf(mxx, xh);
        mny = fminf(mny, yh); mxy = fmaxf(mxy, yh);
        mnz = fminf(mnz, zh); mxz = fmaxf(mxz, zh);
    }
    if (t == 0)    g_pts[chain][0] = make_float4(0.f, 0.f, 0.f, 0.f);
    if (t == 1023) lastpt_s = mylast;   // point 8192

    // two-level bounds via xor-shuffle (width 16):
    // after d=1,2: groups of 4 threads = 32-point subchunk [32c+1, 32c+33)
    // after d=4,8: groups of 16 threads = 128-point chunk
    // +SS inflation covers the left boundary point in both cases.
    #pragma unroll
    for (int d = 1; d < 4; d <<= 1) {
        mnx = fminf(mnx, __shfl_xor_sync(0xffffffffu, mnx, d, 16));
        mxx = fmaxf(mxx, __shfl_xor_sync(0xffffffffu, mxx, d, 16));
        mny = fminf(mny, __shfl_xor_sync(0xffffffffu, mny, d, 16));
        mxy = fmaxf(mxy, __shfl_xor_sync(0xffffffffu, mxy, d, 16));
        mnz = fminf(mnz, __shfl_xor_sync(0xffffffffu, mnz, d, 16));
        mxz = fmaxf(mxz, __shfl_xor_sync(0xffffffffu, mxz, d, 16));
    }
    if ((t & 3) == 0) {
        float hx = 0.5f * (mxx - mnx), hy = 0.5f * (mxy - mny), hz = 0.5f * (mxz - mnz);
        float r = sqrtf(hx * hx + hy * hy + hz * hz) + SS + 1e-2f;
        g_cb32[chain][t >> 2] = make_float4(0.5f * (mnx + mxx), 0.5f * (mny + mxy),
                                            0.5f * (mnz + mxz), r);
    }
    #pragma unroll
    for (int d = 4; d < 16; d <<= 1) {
        mnx = fminf(mnx, __shfl_xor_sync(0xffffffffu, mnx, d, 16));
        mxx = fmaxf(mxx, __shfl_xor_sync(0xffffffffu, mxx, d, 16));
        mny = fminf(mny, __shfl_xor_sync(0xffffffffu, mny, d, 16));
        mxy = fmaxf(mxy, __shfl_xor_sync(0xffffffffu, mxy, d, 16));
        mnz = fminf(mnz, __shfl_xor_sync(0xffffffffu, mnz, d, 16));
        mxz = fmaxf(mxz, __shfl_xor_sync(0xffffffffu, mxz, d, 16));
    }
    if ((t & 15) == 0) {
        float hx = 0.5f * (mxx - mnx), hy = 0.5f * (mxy - mny), hz = 0.5f * (mxz - mnz);
        float r = sqrtf(hx * hx + hy * hy + hz * hz) + SS + 1e-2f;
        g_cb[chain][t >> 4] = make_float4(0.5f * (mnx + mxx), 0.5f * (mny + mxy),
                                          0.5f * (mnz + mxz), r);
    }
    __syncthreads();

    // pads at lastpt with a=-1e30 (exp2 underflows to exactly 0)
    if (t < PADN - NPTS)
        g_pts[chain][NPTS + t] =
            make_float4(lastpt_s.x, lastpt_s.y, lastpt_s.z, -1e30f);

    // sentinels: coarse chunk 64 / sub 256 contain real point 8192 + pads;
    // the rest are pure pads -> far-away centers cull instantly.
    if (t == 0) {
        g_cb[chain][64]    = make_float4(lastpt_s.x, lastpt_s.y, lastpt_s.z, 0.1f);
        g_cb32[chain][256] = make_float4(lastpt_s.x, lastpt_s.y, lastpt_s.z, 0.05f);
    }
    if (t >= 1 && t <= 3)
        g_cb[chain][64 + t] = make_float4(2e15f, 2e15f, 2e15f, 0.f);
    if (t >= 4 && t <= 18)
        g_cb32[chain][256 + t - 3] = make_float4(2e15f, 2e15f, 2e15f, 0.f);
}

// ---------------------------------------------------------------------------
// 32x32 sub-tile: lane = i, loop 32 j's (broadcast loads), 4 ILP chains.
// ---------------------------------------------------------------------------
template <bool DIAG>
__device__ __forceinline__ float tile32(const float4* __restrict__ jp,
                                        float4 ip, int lane) {
    float a0 = 0.f, a1 = 0.f, a2 = 0.f, a3 = 0.f;
    #pragma unroll
    for (int jj = 0; jj < 32; jj += 4) {
        float4 q0 = jp[jj];
        float4 q1 = jp[jj + 1];
        float4 q2 = jp[jj + 2];
        float4 q3 = jp[jj + 3];
        float m0 = fmaf(ip.x, q0.x, q0.w);
        float m1 = fmaf(ip.x, q1.x, q1.w);
        float m2 = fmaf(ip.x, q2.x, q2.w);
        float m3 = fmaf(ip.x, q3.x, q3.w);
        m0 = fmaf(ip.y, q0.y, m0);
        m1 = fmaf(ip.y, q1.y, m1);
        m2 = fmaf(ip.y, q2.y, m2);
        m3 = fmaf(ip.y, q3.y, m3);
        m0 = fmaf(ip.z, q0.z, m0);
        m1 = fmaf(ip.z, q1.z, m1);
        m2 = fmaf(ip.z, q2.z, m2);
        m3 = fmaf(ip.z, q3.z, m3);
        float e0, e1, e2, e3;
        asm("ex2.approx.f32 %0, %1;" : "=f"(e0) : "f"(m0 + ip.w));
        asm("ex2.approx.f32 %0, %1;" : "=f"(e1) : "f"(m1 + ip.w));
        asm("ex2.approx.f32 %0, %1;" : "=f"(e2) : "f"(m2 + ip.w));
        asm("ex2.approx.f32 %0, %1;" : "=f"(e3) : "f"(m3 + ip.w));
        if (DIAG) {
            a0 += (jj     > lane) ? e0 : 0.f;    // strict upper triangle
            a1 += (jj + 1 > lane) ? e1 : 0.f;
            a2 += (jj + 2 > lane) ? e2 : 0.f;
            a3 += (jj + 3 > lane) ? e3 : 0.f;
        } else {
            a0 += e0; a1 += e1; a2 += e2; a3 += e3;
        }
    }
    return (a0 + a1) + (a2 + a3);
}

// ---------------------------------------------------------------------------
// Pair kernel: one block per coarse chunk pair (closed-form decode), coarse
// bounding-sphere cull; live blocks sub-cull 32x32 tiles (warp w = i-sub w).
// Per-block fixed-point quantization -> order-independent sum; last block
// finalizes output and resets state for the next graph replay.
// ---------------------------------------------------------------------------
__global__ void __launch_bounds__(PBLOCK)
pair_kernel(float* __restrict__ out) {
    const int p = blockIdx.x;
    const int chain = blockIdx.y;
    const int tid = threadIdx.x;
    const int lane = tid & 31;
    const int w = tid >> 5;

    // closed-form triangular decode: S(ti) = ti*(137-ti)/2
    float disc = 18769.0f - 8.0f * (float)p;      // 137^2 - 8p
    int ti = (int)((137.0f - sqrtf(disc)) * 0.5f);
    if (ti < 0) ti = 0;
    if (ti > NT - 1) ti = NT - 1;
    while (ti > 0 && (ti * (137 - ti)) / 2 > p) ti--;
    while (((ti + 1) * (136 - ti)) / 2 <= p) ti++;
    const int tj = ti + (p - (ti * (137 - ti)) / 2);

    // coarse cull
    float4 bi = g_cb[chain][ti];
    float4 bj = g_cb[chain][tj];
    float dcx = bi.x - bj.x, dcy = bi.y - bj.y, dcz = bi.z - bj.z;
    float rr = bi.w + bj.w + DCUT_HAT;
    const bool live = (dcx * dcx + dcy * dcy + dcz * dcz <= rr * rr);

    float wsum = 0.f;
    if (live) {
        const int isub = ti * 4 + w;
        const float4* __restrict__ pts = g_pts[chain];
        float4 ip = pts[isub * 32 + lane];
        float4 b32i = g_cb32[chain][isub];

        const int js0 = (ti == tj) ? w : 0;
        for (int js = js0; js < 4; js++) {
            const int jsub = tj * 4 + js;
            float4 b32j = g_cb32[chain][jsub];
            float ex = b32i.x - b32j.x, ey = b32i.y - b32j.y, ez = b32i.z - b32j.z;
            float r2 = b32i.w + b32j.w + DCUT_HAT;
            if (ex * ex + ey * ey + ez * ez <= r2 * r2) {
                const float4* jp = &pts[jsub * 32];
                if (ti == tj && js == w)
                    wsum += tile32<true>(jp, ip, lane);
                else
                    wsum += tile32<false>(jp, ip, lane);
            }
        }
        #pragma unroll
        for (int d = 16; d > 0; d >>= 1)
            wsum += __shfl_down_sync(0xffffffffu, wsum, d);
    }

    __shared__ float red[PBLOCK / 32];
    if (lane == 0) red[w] = wsum;
    __syncthreads();

    if (tid == 0) {
        float tot = red[0] + red[1] + red[2] + red[3];
        if (live && tot > 0.f)
            atomicAdd(&g_acc, (unsigned long long)__float2ll_rn(tot * FXSCALE));
        __threadfence();
        unsigned int done = atomicAdd(&g_count, 1u);
        if (done == NB - 1) {
            unsigned long long raw = atomicAdd(&g_acc, 0ULL);
            double sum = (double)(long long)raw * (1.0 / (double)FXSCALE);
            out[0] = (float)(10.0 * (2.0 * sum + (double)(NCHAIN * NPTS)));
            // reset for next graph replay
            atomicExch(&g_acc, 0ULL);
            atomicExch(&g_count, 0u);
        }
    }
}

extern "C" void kernel_launch(void* const* d_in, const int* in_sizes, int n_in,
                              void* d_out, int out_size) {
    const float* conf = (const float*)d_in[0];
    float* out = (float*)d_out;

    setup_kernel<<<NCHAIN, 1024>>>(conf);
    pair_kernel<<<dim3(NP, NCHAIN), PBLOCK>>>(out);
}

// round 13
// speedup vs baseline: 1.3988x; 1.3262x over previous
#include <cuda_runtime.h>

// Problem constants
#define NPTS     8193            // positions per chain (incl. leading zero row)
#define NCHAIN   2
#define CONFLEN  16388

// 32-point sub-chunks, pair space culled lane-parallel in the pair kernel
#define NSUB     272                             // PADN / 32
#define PADN     (NSUB * 32)                     // 8704
#define NSUBP    (NSUB * (NSUB + 1) / 2)         // 37128 fine pairs per chain
#define TOTQ     (NSUBP * NCHAIN)                // 74256

#define PBLOCK   512
#define PGRID    148                             // one wave
#define NWARPS   (PGRID * (PBLOCK / 32))         // 2368

// Scaled-space cutoff: dropped pair value <= 2^(-0.5*64) = 2.3e-10
#define DCUT_HAT 8.0f

// Fixed-point scale for deterministic integer accumulation
#define FXSCALE  16777216.0f     // 2^24

// Scratch (no allocations allowed; zero-initialized at load)
__device__ float4 g_pts[NCHAIN][PADN];           // (x_hat, y_hat, z_hat, a)
__device__ float4 g_cb32[NCHAIN][NSUB];          // fine bounds (cx,cy,cz,r)
__device__ unsigned long long g_acc;             // fixed-point sum
__device__ unsigned int g_count;                 // finished-block counter

// ---------------------------------------------------------------------------
// Setup: one block (1024 threads) per chain, 8 steps/thread register-resident
// prefix sum; emits scaled points, pads, and 32-point sub-chunk bounds.
// ---------------------------------------------------------------------------
__global__ void __launch_bounds__(1024)
setup_kernel(const float* __restrict__ conf) {
    const int chain = blockIdx.x;
    const int t = threadIdx.x;
    const int lane = t & 31, warp = t >> 5;
    const float2* cp = (const float2*)(conf + chain * CONFLEN + 4);
    const float TWO_PI = 6.2831853071795864769f;

    float px[8], py[8], pz[8];
    float sx = 0.f, sy = 0.f, sz = 0.f;
    #pragma unroll
    for (int m = 0; m < 8; m++) {
        float2 rr = cp[t * 8 + m];
        float r1 = rr.x + 0.5f;
        float r2 = rr.y + 0.5f;
        float z  = 1.0f - 2.0f * r2;                   // cos(theta)
        float sth = sqrtf(fmaxf(1.0f - z * z, 0.0f));  // sin(theta)
        float s, c;
        __sincosf(r1 * TWO_PI, &s, &c);
        sx += sth * c;
        sy += sth * s;
        sz += z;
        px[m] = sx; py[m] = sy; pz[m] = sz;
    }

    // warp inclusive scan of thread totals
    float tx = sx, ty = sy, tz = sz;
    #pragma unroll
    for (int d = 1; d < 32; d <<= 1) {
        float ox = __shfl_up_sync(0xffffffffu, tx, d);
        float oy = __shfl_up_sync(0xffffffffu, ty, d);
        float oz = __shfl_up_sync(0xffffffffu, tz, d);
        if (lane >= d) { tx += ox; ty += oy; tz += oz; }
    }

    __shared__ float3 wtot[32], woff[32];
    __shared__ float4 lastpt_s;
    if (lane == 31) wtot[warp] = make_float3(tx, ty, tz);
    __syncthreads();
    if (t == 0) {
        float ax = 0.f, ay = 0.f, az = 0.f;
        #pragma unroll
        for (int w = 0; w < 32; w++) {
            float3 v = wtot[w];
            woff[w] = make_float3(ax, ay, az);
            ax += v.x; ay += v.y; az += v.z;
        }
    }
    __syncthreads();
    float bx = woff[warp].x + (tx - sx);
    float by = woff[warp].y + (ty - sy);
    float bz = woff[warp].z + (tz - sz);

    // arg = a_i + a_j + dot(p_hat_i, p_hat_j), p_hat = SS*p, a=-0.5|p_hat|^2
    const float S2 = 8.0f * 1.4426950408889634f;   // 8*log2(e)
    const float SS = sqrtf(S2);                    // scaled step length

    float4 mylast = make_float4(0.f, 0.f, 0.f, 0.f);
    float mnx = 1e30f, mxx = -1e30f, mny = 1e30f, mxy = -1e30f;
    float mnz = 1e30f, mxz = -1e30f;
    #pragma unroll
    for (int m = 0; m < 8; m++) {
        float xh = SS * (bx + px[m]);
        float yh = SS * (by + py[m]);
        float zh = SS * (bz + pz[m]);
        float a = -0.5f * (xh * xh + yh * yh + zh * zh);
        mylast = make_float4(xh, yh, zh, a);
        g_pts[chain][t * 8 + m + 1] = mylast;
        mnx = fminf(mnx, xh); mxx = fmaxf(mxx, xh);
        mny = fminf(mny, yh); mxy = fmaxf(mxy, yh);
        mnz = fminf(mnz, zh); mxz = fmaxf(mxz, zh);
    }
    if (t == 0)    g_pts[chain][0] = make_float4(0.f, 0.f, 0.f, 0.f);
    if (t == 1023) lastpt_s = mylast;   // point 8192

    // fine bounds: threads 4c..4c+3 cover points [32c+1, 32c+33);
    // +SS inflation covers the left boundary point 32c.
    #pragma unroll
    for (int d = 1; d < 4; d <<= 1) {
        mnx = fminf(mnx, __shfl_xor_sync(0xffffffffu, mnx, d, 4));
        mxx = fmaxf(mxx, __shfl_xor_sync(0xffffffffu, mxx, d, 4));
        mny = fminf(mny, __shfl_xor_sync(0xffffffffu, mny, d, 4));
        mxy = fmaxf(mxy, __shfl_xor_sync(0xffffffffu, mxy, d, 4));
        mnz = fminf(mnz, __shfl_xor_sync(0xffffffffu, mnz, d, 4));
        mxz = fmaxf(mxz, __shfl_xor_sync(0xffffffffu, mxz, d, 4));
    }
    if ((t & 3) == 0) {
        float hx = 0.5f * (mxx - mnx), hy = 0.5f * (mxy - mny), hz = 0.5f * (mxz - mnz);
        float r = sqrtf(hx * hx + hy * hy + hz * hz) + SS + 1e-2f;
        g_cb32[chain][t >> 2] = make_float4(0.5f * (mnx + mxx), 0.5f * (mny + mxy),
                                            0.5f * (mnz + mxz), r);
    }
    __syncthreads();

    // pads at lastpt with a=-1e30 (exp2 underflows to exactly 0)
    if (t < PADN - NPTS)
        g_pts[chain][NPTS + t] =
            make_float4(lastpt_s.x, lastpt_s.y, lastpt_s.z, -1e30f);

    // sub-chunk 256 holds real point 8192 + pads at lastpt; 257..271 pure pads
    if (t == 0)
        g_cb32[chain][256] = make_float4(lastpt_s.x, lastpt_s.y, lastpt_s.z, 0.05f);
    if (t >= 4 && t <= 18)
        g_cb32[chain][256 + t - 3] = make_float4(2e15f, 2e15f, 2e15f, 0.f);
}

// ---------------------------------------------------------------------------
// 32x32 sub-tile: lane = i, loop 32 j's (broadcast loads), 4 ILP chains.
// Returns this lane's partial (no reduction here).
// ---------------------------------------------------------------------------
template <bool DIAG>
__device__ __forceinline__ float tile32(const float4* __restrict__ jp,
                                        float4 ip, int lane) {
    float a0 = 0.f, a1 = 0.f, a2 = 0.f, a3 = 0.f;
    #pragma unroll
    for (int jj = 0; jj < 32; jj += 4) {
        float4 q0 = __ldg(&jp[jj]);
        float4 q1 = __ldg(&jp[jj + 1]);
        float4 q2 = __ldg(&jp[jj + 2]);
        float4 q3 = __ldg(&jp[jj + 3]);
        float m0 = fmaf(ip.x, q0.x, q0.w);
        float m1 = fmaf(ip.x, q1.x, q1.w);
        float m2 = fmaf(ip.x, q2.x, q2.w);
        float m3 = fmaf(ip.x, q3.x, q3.w);
        m0 = fmaf(ip.y, q0.y, m0);
        m1 = fmaf(ip.y, q1.y, m1);
        m2 = fmaf(ip.y, q2.y, m2);
        m3 = fmaf(ip.y, q3.y, m3);
        m0 = fmaf(ip.z, q0.z, m0);
        m1 = fmaf(ip.z, q1.z, m1);
        m2 = fmaf(ip.z, q2.z, m2);
        m3 = fmaf(ip.z, q3.z, m3);
        float e0, e1, e2, e3;
        asm("ex2.approx.f32 %0, %1;" : "=f"(e0) : "f"(m0 + ip.w));
        asm("ex2.approx.f32 %0, %1;" : "=f"(e1) : "f"(m1 + ip.w));
        asm("ex2.approx.f32 %0, %1;" : "=f"(e2) : "f"(m2 + ip.w));
        asm("ex2.approx.f32 %0, %1;" : "=f"(e3) : "f"(m3 + ip.w));
        if (DIAG) {
            a0 += (jj     > lane) ? e0 : 0.f;    // strict upper triangle
            a1 += (jj + 1 > lane) ? e1 : 0.f;
            a2 += (jj + 2 > lane) ? e2 : 0.f;
            a3 += (jj + 3 > lane) ? e3 : 0.f;
        } else {
            a0 += e0; a1 += e1; a2 += e2; a3 += e3;
        }
    }
    return (a0 + a1) + (a2 + a3);
}

// ---------------------------------------------------------------------------
// Pair kernel: 148 blocks x 512 (one wave, 2368 warps). Warp g owns fine-pair
// indices q = g + lane*NWARPS (ONE lane-parallel cull round, one ballot),
// then walks its live mask processing 32x32 tiles as a full warp. One warp
// reduction at the end; per-warp fixed-point quantize (deterministic);
// block smem-reduce -> 148 atomics. Last block finalizes + resets.
// ---------------------------------------------------------------------------
__global__ void __launch_bounds__(PBLOCK)
pair_kernel(float* __restrict__ out) {
    const int tid = threadIdx.x;
    const int lane = tid & 31;
    const int w = tid >> 5;
    const unsigned int gw = blockIdx.x * (PBLOCK / 32) + w;

    // lane-parallel cull: q = gw + lane*NWARPS  (covers [0, TOTQ) exactly)
    unsigned int q = gw + (unsigned int)lane * NWARPS;
    bool pred = false;
    int packed = 0;
    if (q < TOTQ) {
        int chain = (q >= NSUBP) ? 1 : 0;
        int p = (int)q - chain * NSUBP;
        // triangular decode over N=272: S(ci) = ci*(545-ci)/2
        float disc = 297025.0f - 8.0f * (float)p;     // 545^2 - 8p (exact fp32)
        int ci = (int)((545.0f - sqrtf(disc)) * 0.5f);
        if (ci < 0) ci = 0;
        if (ci > NSUB - 1) ci = NSUB - 1;
        while (ci > 0 && (ci * (545 - ci)) / 2 > p) ci--;
        while (((ci + 1) * (544 - ci)) / 2 <= p) ci++;
        int cj = ci + (p - (ci * (545 - ci)) / 2);

        float4 bi = g_cb32[chain][ci];
        float4 bj = g_cb32[chain][cj];
        float dx = bi.x - bj.x, dy = bi.y - bj.y, dz = bi.z - bj.z;
        float rr = bi.w + bj.w + DCUT_HAT;
        pred = (dx * dx + dy * dy + dz * dz <= rr * rr);
        packed = (chain << 20) | (ci << 10) | cj;
    }

    unsigned int mask = __ballot_sync(0xffffffffu, pred);
    float acc = 0.f;
    while (mask) {
        int b = __ffs(mask) - 1;
        mask &= mask - 1;
        int item = __shfl_sync(0xffffffffu, packed, b);
        int chain = item >> 20;
        int ci = (item >> 10) & 1023;
        int cj = item & 1023;
        const float4* jp = &g_pts[chain][cj * 32];
        float4 ip = g_pts[chain][ci * 32 + lane];
        if (ci == cj) acc += tile32<true>(jp, ip, lane);
        else          acc += tile32<false>(jp, ip, lane);
    }

    // single warp reduction, per-warp quantize (fixed item order -> determ.)
    #pragma unroll
    for (int d = 16; d > 0; d >>= 1)
        acc += __shfl_down_sync(0xffffffffu, acc, d);

    __shared__ unsigned long long wred[PBLOCK / 32];
    if (lane == 0)
        wred[w] = (unsigned long long)__float2ll_rn(acc * FXSCALE);
    __syncthreads();

    if (tid == 0) {
        unsigned long long s = 0ULL;
        #pragma unroll
        for (int k = 0; k < PBLOCK / 32; k++) s += wred[k];
        if (s) atomicAdd(&g_acc, s);
        __threadfence();
        unsigned int done = atomicAdd(&g_count, 1u);
        if (done == PGRID - 1) {
            unsigned long long raw = atomicAdd(&g_acc, 0ULL);
            double sum = (double)(long long)raw * (1.0 / (double)FXSCALE);
            out[0] = (float)(10.0 * (2.0 * sum + (double)(NCHAIN * NPTS)));
            // reset for next graph replay
            atomicExch(&g_acc, 0ULL);
            atomicExch(&g_count, 0u);
        }
    }
}

extern "C" void kernel_launch(void* const* d_in, const int* in_sizes, int n_in,
                              void* d_out, int out_size) {
    const float* conf = (const float*)d_in[0];
    float* out = (float*)d_out;

    setup_kernel<<<NCHAIN, 1024>>>(conf);
    pair_kernel<<<PGRID, PBLOCK>>>(out);
}

// round 14
// speedup vs baseline: 1.5981x; 1.1425x over previous
#include <cuda_runtime.h>

// Problem constants
#define NPTS     8193            // positions per chain (incl. leading zero row)
#define NCHAIN   2
#define CONFLEN  16388

// 32-point sub-chunks, pair space culled lane-parallel in the pair kernel
#define NSUB     272                             // PADN / 32
#define PADN     (NSUB * 32)                     // 8704
#define NSUBP    (NSUB * (NSUB + 1) / 2)         // 37128 fine pairs per chain
#define TOTQ     (NSUBP * NCHAIN)                // 74256

#define PBLOCK   256
#define PGRID    888                             // 6 blocks/SM, 48 warps/SM
#define NWARPS   (PGRID * (PBLOCK / 32))         // 7104

// Scaled-space cutoff: dropped pair value <= 2^(-0.5*64) = 2.3e-10
#define DCUT_HAT 8.0f

// Fixed-point scale for deterministic integer accumulation
#define FXSCALE  16777216.0f     // 2^24

// Scratch (no allocations allowed; zero-initialized at load)
__device__ float4 g_pts[NCHAIN][PADN];           // (x_hat, y_hat, z_hat, a)
__device__ float4 g_cb32[NCHAIN][NSUB];          // fine bounds (cx,cy,cz,r)
__device__ unsigned long long g_acc;             // fixed-point sum
__device__ unsigned int g_count;                 // finished-block counter

// ---------------------------------------------------------------------------
// Setup: one block (1024 threads) per chain, 8 steps/thread register-resident
// prefix sum; emits scaled points, pads, and 32-point sub-chunk bounds.
// ---------------------------------------------------------------------------
__global__ void __launch_bounds__(1024)
setup_kernel(const float* __restrict__ conf) {
    const int chain = blockIdx.x;
    const int t = threadIdx.x;
    const int lane = t & 31, warp = t >> 5;
    const float2* cp = (const float2*)(conf + chain * CONFLEN + 4);
    const float TWO_PI = 6.2831853071795864769f;

    float px[8], py[8], pz[8];
    float sx = 0.f, sy = 0.f, sz = 0.f;
    #pragma unroll
    for (int m = 0; m < 8; m++) {
        float2 rr = cp[t * 8 + m];
        float r1 = rr.x + 0.5f;
        float r2 = rr.y + 0.5f;
        float z  = 1.0f - 2.0f * r2;                   // cos(theta)
        float sth = sqrtf(fmaxf(1.0f - z * z, 0.0f));  // sin(theta)
        float s, c;
        __sincosf(r1 * TWO_PI, &s, &c);
        sx += sth * c;
        sy += sth * s;
        sz += z;
        px[m] = sx; py[m] = sy; pz[m] = sz;
    }

    // warp inclusive scan of thread totals
    float tx = sx, ty = sy, tz = sz;
    #pragma unroll
    for (int d = 1; d < 32; d <<= 1) {
        float ox = __shfl_up_sync(0xffffffffu, tx, d);
        float oy = __shfl_up_sync(0xffffffffu, ty, d);
        float oz = __shfl_up_sync(0xffffffffu, tz, d);
        if (lane >= d) { tx += ox; ty += oy; tz += oz; }
    }

    __shared__ float3 wtot[32], woff[32];
    __shared__ float4 lastpt_s;
    if (lane == 31) wtot[warp] = make_float3(tx, ty, tz);
    __syncthreads();
    if (t == 0) {
        float ax = 0.f, ay = 0.f, az = 0.f;
        #pragma unroll
        for (int w = 0; w < 32; w++) {
            float3 v = wtot[w];
            woff[w] = make_float3(ax, ay, az);
            ax += v.x; ay += v.y; az += v.z;
        }
    }
    __syncthreads();
    float bx = woff[warp].x + (tx - sx);
    float by = woff[warp].y + (ty - sy);
    float bz = woff[warp].z + (tz - sz);

    // arg = a_i + a_j + dot(p_hat_i, p_hat_j), p_hat = SS*p, a=-0.5|p_hat|^2
    const float S2 = 8.0f * 1.4426950408889634f;   // 8*log2(e)
    const float SS = sqrtf(S2);                    // scaled step length

    float4 mylast = make_float4(0.f, 0.f, 0.f, 0.f);
    float mnx = 1e30f, mxx = -1e30f, mny = 1e30f, mxy = -1e30f;
    float mnz = 1e30f, mxz = -1e30f;
    #pragma unroll
    for (int m = 0; m < 8; m++) {
        float xh = SS * (bx + px[m]);
        float yh = SS * (by + py[m]);
        float zh = SS * (bz + pz[m]);
        float a = -0.5f * (xh * xh + yh * yh + zh * zh);
        mylast = make_float4(xh, yh, zh, a);
        g_pts[chain][t * 8 + m + 1] = mylast;
        mnx = fminf(mnx, xh); mxx = fmaxf(mxx, xh);
        mny = fminf(mny, yh); mxy = fmaxf(mxy, yh);
        mnz = fminf(mnz, zh); mxz = fmaxf(mxz, zh);
    }
    if (t == 0)    g_pts[chain][0] = make_float4(0.f, 0.f, 0.f, 0.f);
    if (t == 1023) lastpt_s = mylast;   // point 8192

    // fine bounds: threads 4c..4c+3 cover points [32c+1, 32c+33);
    // +SS inflation covers the left boundary point 32c.
    #pragma unroll
    for (int d = 1; d < 4; d <<= 1) {
        mnx = fminf(mnx, __shfl_xor_sync(0xffffffffu, mnx, d, 4));
        mxx = fmaxf(mxx, __shfl_xor_sync(0xffffffffu, mxx, d, 4));
        mny = fminf(mny, __shfl_xor_sync(0xffffffffu, mny, d, 4));
        mxy = fmaxf(mxy, __shfl_xor_sync(0xffffffffu, mxy, d, 4));
        mnz = fminf(mnz, __shfl_xor_sync(0xffffffffu, mnz, d, 4));
        mxz = fmaxf(mxz, __shfl_xor_sync(0xffffffffu, mxz, d, 4));
    }
    if ((t & 3) == 0) {
        float hx = 0.5f * (mxx - mnx), hy = 0.5f * (mxy - mny), hz = 0.5f * (mxz - mnz);
        float r = sqrtf(hx * hx + hy * hy + hz * hz) + SS + 1e-2f;
        g_cb32[chain][t >> 2] = make_float4(0.5f * (mnx + mxx), 0.5f * (mny + mxy),
                                            0.5f * (mnz + mxz), r);
    }
    __syncthreads();

    // pads at lastpt with a=-1e30 (exp2 underflows to exactly 0)
    if (t < PADN - NPTS)
        g_pts[chain][NPTS + t] =
            make_float4(lastpt_s.x, lastpt_s.y, lastpt_s.z, -1e30f);

    // sub-chunk 256 holds real point 8192 + pads at lastpt; 257..271 pure pads
    if (t == 0)
        g_cb32[chain][256] = make_float4(lastpt_s.x, lastpt_s.y, lastpt_s.z, 0.05f);
    if (t >= 4 && t <= 18)
        g_cb32[chain][256 + t - 3] = make_float4(2e15f, 2e15f, 2e15f, 0.f);
}

// ---------------------------------------------------------------------------
// 32x32 sub-tile: lane = i, loop 32 j's (broadcast loads), 4 ILP chains.
// Returns this lane's partial (no reduction here).
// ---------------------------------------------------------------------------
template <bool DIAG>
__device__ __forceinline__ float tile32(const float4* __restrict__ jp,
                                        float4 ip, int lane) {
    float a0 = 0.f, a1 = 0.f, a2 = 0.f, a3 = 0.f;
    #pragma unroll
    for (int jj = 0; jj < 32; jj += 4) {
        float4 q0 = __ldg(&jp[jj]);
        float4 q1 = __ldg(&jp[jj + 1]);
        float4 q2 = __ldg(&jp[jj + 2]);
        float4 q3 = __ldg(&jp[jj + 3]);
        float m0 = fmaf(ip.x, q0.x, q0.w);
        float m1 = fmaf(ip.x, q1.x, q1.w);
        float m2 = fmaf(ip.x, q2.x, q2.w);
        float m3 = fmaf(ip.x, q3.x, q3.w);
        m0 = fmaf(ip.y, q0.y, m0);
        m1 = fmaf(ip.y, q1.y, m1);
        m2 = fmaf(ip.y, q2.y, m2);
        m3 = fmaf(ip.y, q3.y, m3);
        m0 = fmaf(ip.z, q0.z, m0);
        m1 = fmaf(ip.z, q1.z, m1);
        m2 = fmaf(ip.z, q2.z, m2);
        m3 = fmaf(ip.z, q3.z, m3);
        float e0, e1, e2, e3;
        asm("ex2.approx.f32 %0, %1;" : "=f"(e0) : "f"(m0 + ip.w));
        asm("ex2.approx.f32 %0, %1;" : "=f"(e1) : "f"(m1 + ip.w));
        asm("ex2.approx.f32 %0, %1;" : "=f"(e2) : "f"(m2 + ip.w));
        asm("ex2.approx.f32 %0, %1;" : "=f"(e3) : "f"(m3 + ip.w));
        if (DIAG) {
            a0 += (jj     > lane) ? e0 : 0.f;    // strict upper triangle
            a1 += (jj + 1 > lane) ? e1 : 0.f;
            a2 += (jj + 2 > lane) ? e2 : 0.f;
            a3 += (jj + 3 > lane) ? e3 : 0.f;
        } else {
            a0 += e0; a1 += e1; a2 += e2; a3 += e3;
        }
    }
    return (a0 + a1) + (a2 + a3);
}

// ---------------------------------------------------------------------------
// Pair kernel: 888 blocks x 256 (6 blocks/SM, 48 warps/SM). Warp g owns
// fine-pair indices q = g + lane*NWARPS (ONE lane-parallel cull round, one
// ballot), then walks its live mask processing 32x32 tiles as a full warp.
// One warp reduction at the end; per-warp fixed-point quantize; block
// smem-reduce -> 888 atomics. Last block finalizes + resets.
// ---------------------------------------------------------------------------
__global__ void __launch_bounds__(PBLOCK)
pair_kernel(float* __restrict__ out) {
    const int tid = threadIdx.x;
    const int lane = tid & 31;
    const int w = tid >> 5;
    const unsigned int gw = blockIdx.x * (PBLOCK / 32) + w;

    // lane-parallel cull: q = gw + lane*NWARPS  (covers [0, TOTQ) exactly)
    unsigned int q = gw + (unsigned int)lane * NWARPS;
    bool pred = false;
    int packed = 0;
    if (q < TOTQ) {
        int chain = (q >= NSUBP) ? 1 : 0;
        int p = (int)q - chain * NSUBP;
        // triangular decode over N=272: S(ci) = ci*(545-ci)/2
        float disc = 297025.0f - 8.0f * (float)p;     // 545^2 - 8p (exact fp32)
        int ci = (int)((545.0f - sqrtf(disc)) * 0.5f);
        if (ci < 0) ci = 0;
        if (ci > NSUB - 1) ci = NSUB - 1;
        while (ci > 0 && (ci * (545 - ci)) / 2 > p) ci--;
        while (((ci + 1) * (544 - ci)) / 2 <= p) ci++;
        int cj = ci + (p - (ci * (545 - ci)) / 2);

        float4 bi = g_cb32[chain][ci];
        float4 bj = g_cb32[chain][cj];
        float dx = bi.x - bj.x, dy = bi.y - bj.y, dz = bi.z - bj.z;
        float rr = bi.w + bj.w + DCUT_HAT;
        pred = (dx * dx + dy * dy + dz * dz <= rr * rr);
        packed = (chain << 20) | (ci << 10) | cj;
    }

    unsigned int mask = __ballot_sync(0xffffffffu, pred);
    float acc = 0.f;
    while (mask) {
        int b = __ffs(mask) - 1;
        mask &= mask - 1;
        int item = __shfl_sync(0xffffffffu, packed, b);
        int chain = item >> 20;
        int ci = (item >> 10) & 1023;
        int cj = item & 1023;
        const float4* jp = &g_pts[chain][cj * 32];
        float4 ip = g_pts[chain][ci * 32 + lane];
        if (ci == cj) acc += tile32<true>(jp, ip, lane);
        else          acc += tile32<false>(jp, ip, lane);
    }

    // single warp reduction, per-warp quantize (fixed item order -> determ.)
    #pragma unroll
    for (int d = 16; d > 0; d >>= 1)
        acc += __shfl_down_sync(0xffffffffu, acc, d);

    __shared__ unsigned long long wred[PBLOCK / 32];
    if (lane == 0)
        wred[w] = (unsigned long long)__float2ll_rn(acc * FXSCALE);
    __syncthreads();

    if (tid == 0) {
        unsigned long long s = 0ULL;
        #pragma unroll
        for (int k = 0; k < PBLOCK / 32; k++) s += wred[k];
        if (s) atomicAdd(&g_acc, s);
        __threadfence();
        unsigned int done = atomicAdd(&g_count, 1u);
        if (done == PGRID - 1) {
            unsigned long long raw = atomicAdd(&g_acc, 0ULL);
            double sum = (double)(long long)raw * (1.0 / (double)FXSCALE);
            out[0] = (float)(10.0 * (2.0 * sum + (double)(NCHAIN * NPTS)));
            // reset for next graph replay
            atomicExch(&g_acc, 0ULL);
            atomicExch(&g_count, 0u);
        }
    }
}

extern "C" void kernel_launch(void* const* d_in, const int* in_sizes, int n_in,
                              void* d_out, int out_size) {
    const float* conf = (const float*)d_in[0];
    float* out = (float*)d_out;

    setup_kernel<<<NCHAIN, 1024>>>(conf);
    pair_kernel<<<PGRID, PBLOCK>>>(out);
}

// round 15
// speedup vs baseline: 1.7449x; 1.0918x over previous
#include <cuda_runtime.h>

// Problem constants
#define NPTS     8193            // positions per chain (incl. leading zero row)
#define NCHAIN   2
#define CONFLEN  16388

// 32-point sub-chunks, pair space culled lane-parallel in the pair kernel
#define NSUB     272                             // PADN / 32
#define PADN     (NSUB * 32)                     // 8704
#define NSUBP    (NSUB * (NSUB + 1) / 2)         // 37128 fine pairs per chain
#define TOTQ     (NSUBP * NCHAIN)                // 74256

#define PBLOCK   256
#define PGRID    888                             // 6 blocks/SM
#define QPB      ((TOTQ + PGRID - 1) / PGRID)    // 84 q's per block

// Scaled-space cutoff: dropped pair value <= 2^(-0.5*64) = 2.3e-10
#define DCUT_HAT 8.0f

// Fixed-point scale for deterministic integer accumulation
#define FXSCALE  16777216.0f     // 2^24

// Scratch (no allocations allowed; zero-initialized at load)
__device__ float4 g_pts[NCHAIN][PADN];           // (x_hat, y_hat, z_hat, a)
__device__ float4 g_cb32[NCHAIN][NSUB];          // fine bounds (cx,cy,cz,r)
__device__ unsigned long long g_acc;             // fixed-point sum
__device__ unsigned int g_count;                 // finished-block counter

// ---------------------------------------------------------------------------
// Setup: one block (1024 threads) per chain, 8 steps/thread register-resident
// prefix sum; emits scaled points, pads, and 32-point sub-chunk bounds.
// ---------------------------------------------------------------------------
__global__ void __launch_bounds__(1024)
setup_kernel(const float* __restrict__ conf) {
    const int chain = blockIdx.x;
    const int t = threadIdx.x;
    const int lane = t & 31, warp = t >> 5;
    const float2* cp = (const float2*)(conf + chain * CONFLEN + 4);
    const float TWO_PI = 6.2831853071795864769f;

    float px[8], py[8], pz[8];
    float sx = 0.f, sy = 0.f, sz = 0.f;
    #pragma unroll
    for (int m = 0; m < 8; m++) {
        float2 rr = cp[t * 8 + m];
        float r1 = rr.x + 0.5f;
        float r2 = rr.y + 0.5f;
        float z  = 1.0f - 2.0f * r2;                   // cos(theta)
        float sth = sqrtf(fmaxf(1.0f - z * z, 0.0f));  // sin(theta)
        float s, c;
        __sincosf(r1 * TWO_PI, &s, &c);
        sx += sth * c;
        sy += sth * s;
        sz += z;
        px[m] = sx; py[m] = sy; pz[m] = sz;
    }

    // warp inclusive scan of thread totals
    float tx = sx, ty = sy, tz = sz;
    #pragma unroll
    for (int d = 1; d < 32; d <<= 1) {
        float ox = __shfl_up_sync(0xffffffffu, tx, d);
        float oy = __shfl_up_sync(0xffffffffu, ty, d);
        float oz = __shfl_up_sync(0xffffffffu, tz, d);
        if (lane >= d) { tx += ox; ty += oy; tz += oz; }
    }

    __shared__ float3 wtot[32], woff[32];
    __shared__ float4 lastpt_s;
    if (lane == 31) wtot[warp] = make_float3(tx, ty, tz);
    __syncthreads();
    if (t == 0) {
        float ax = 0.f, ay = 0.f, az = 0.f;
        #pragma unroll
        for (int w = 0; w < 32; w++) {
            float3 v = wtot[w];
            woff[w] = make_float3(ax, ay, az);
            ax += v.x; ay += v.y; az += v.z;
        }
    }
    __syncthreads();
    float bx = woff[warp].x + (tx - sx);
    float by = woff[warp].y + (ty - sy);
    float bz = woff[warp].z + (tz - sz);

    // arg = a_i + a_j + dot(p_hat_i, p_hat_j), p_hat = SS*p, a=-0.5|p_hat|^2
    const float S2 = 8.0f * 1.4426950408889634f;   // 8*log2(e)
    const float SS = sqrtf(S2);                    // scaled step length

    float4 mylast = make_float4(0.f, 0.f, 0.f, 0.f);
    float mnx = 1e30f, mxx = -1e30f, mny = 1e30f, mxy = -1e30f;
    float mnz = 1e30f, mxz = -1e30f;
    #pragma unroll
    for (int m = 0; m < 8; m++) {
        float xh = SS * (bx + px[m]);
        float yh = SS * (by + py[m]);
        float zh = SS * (bz + pz[m]);
        float a = -0.5f * (xh * xh + yh * yh + zh * zh);
        mylast = make_float4(xh, yh, zh, a);
        g_pts[chain][t * 8 + m + 1] = mylast;
        mnx = fminf(mnx, xh); mxx = fmaxf(mxx, xh);
        mny = fminf(mny, yh); mxy = fmaxf(mxy, yh);
        mnz = fminf(mnz, zh); mxz = fmaxf(mxz, zh);
    }
    if (t == 0)    g_pts[chain][0] = make_float4(0.f, 0.f, 0.f, 0.f);
    if (t == 1023) lastpt_s = mylast;   // point 8192

    // fine bounds: threads 4c..4c+3 cover points [32c+1, 32c+33);
    // +SS inflation covers the left boundary point 32c.
    #pragma unroll
    for (int d = 1; d < 4; d <<= 1) {
        mnx = fminf(mnx, __shfl_xor_sync(0xffffffffu, mnx, d, 4));
        mxx = fmaxf(mxx, __shfl_xor_sync(0xffffffffu, mxx, d, 4));
        mny = fminf(mny, __shfl_xor_sync(0xffffffffu, mny, d, 4));
        mxy = fmaxf(mxy, __shfl_xor_sync(0xffffffffu, mxy, d, 4));
        mnz = fminf(mnz, __shfl_xor_sync(0xffffffffu, mnz, d, 4));
        mxz = fmaxf(mxz, __shfl_xor_sync(0xffffffffu, mxz, d, 4));
    }
    if ((t & 3) == 0) {
        float hx = 0.5f * (mxx - mnx), hy = 0.5f * (mxy - mny), hz = 0.5f * (mxz - mnz);
        float r = sqrtf(hx * hx + hy * hy + hz * hz) + SS + 1e-2f;
        g_cb32[chain][t >> 2] = make_float4(0.5f * (mnx + mxx), 0.5f * (mny + mxy),
                                            0.5f * (mnz + mxz), r);
    }
    __syncthreads();

    // pads at lastpt with a=-1e30 (exp2 underflows to exactly 0)
    if (t < PADN - NPTS)
        g_pts[chain][NPTS + t] =
            make_float4(lastpt_s.x, lastpt_s.y, lastpt_s.z, -1e30f);

    // sub-chunk 256 holds real point 8192 + pads at lastpt; 257..271 pure pads
    if (t == 0)
        g_cb32[chain][256] = make_float4(lastpt_s.x, lastpt_s.y, lastpt_s.z, 0.05f);
    if (t >= 4 && t <= 18)
        g_cb32[chain][256 + t - 3] = make_float4(2e15f, 2e15f, 2e15f, 0.f);
}

// ---------------------------------------------------------------------------
// 32x32 sub-tile: lane = i, loop 32 j's (broadcast loads), 4 ILP chains.
// Returns this lane's partial (no reduction here).
// ---------------------------------------------------------------------------
template <bool DIAG>
__device__ __forceinline__ float tile32(const float4* __restrict__ jp,
                                        float4 ip, int lane) {
    float a0 = 0.f, a1 = 0.f, a2 = 0.f, a3 = 0.f;
    #pragma unroll
    for (int jj = 0; jj < 32; jj += 4) {
        float4 q0 = __ldg(&jp[jj]);
        float4 q1 = __ldg(&jp[jj + 1]);
        float4 q2 = __ldg(&jp[jj + 2]);
        float4 q3 = __ldg(&jp[jj + 3]);
        float m0 = fmaf(ip.x, q0.x, q0.w);
        float m1 = fmaf(ip.x, q1.x, q1.w);
        float m2 = fmaf(ip.x, q2.x, q2.w);
        float m3 = fmaf(ip.x, q3.x, q3.w);
        m0 = fmaf(ip.y, q0.y, m0);
        m1 = fmaf(ip.y, q1.y, m1);
        m2 = fmaf(ip.y, q2.y, m2);
        m3 = fmaf(ip.y, q3.y, m3);
        m0 = fmaf(ip.z, q0.z, m0);
        m1 = fmaf(ip.z, q1.z, m1);
        m2 = fmaf(ip.z, q2.z, m2);
        m3 = fmaf(ip.z, q3.z, m3);
        float e0, e1, e2, e3;
        asm("ex2.approx.f32 %0, %1;" : "=f"(e0) : "f"(m0 + ip.w));
        asm("ex2.approx.f32 %0, %1;" : "=f"(e1) : "f"(m1 + ip.w));
        asm("ex2.approx.f32 %0, %1;" : "=f"(e2) : "f"(m2 + ip.w));
        asm("ex2.approx.f32 %0, %1;" : "=f"(e3) : "f"(m3 + ip.w));
        if (DIAG) {
            a0 += (jj     > lane) ? e0 : 0.f;    // strict upper triangle
            a1 += (jj + 1 > lane) ? e1 : 0.f;
            a2 += (jj + 2 > lane) ? e2 : 0.f;
            a3 += (jj + 3 > lane) ? e3 : 0.f;
        } else {
            a0 += e0; a1 += e1; a2 += e2; a3 += e3;
        }
    }
    return (a0 + a1) + (a2 + a3);
}

// ---------------------------------------------------------------------------
// Pair kernel: 888 blocks x 256. Block culls its 84 statically-assigned
// q-indices (1/thread) into a SHARED live list; the block's 8 warps then POP
// items dynamically (shared counter) -> intra-block load balancing. Each tile
// is warp-reduced and quantized to fixed point PER ITEM (order-independent),
// accumulated in a shared u64; one global atomic per block. Last block
// finalizes + resets for the next graph replay.
// ---------------------------------------------------------------------------
__global__ void __launch_bounds__(PBLOCK)
pair_kernel(float* __restrict__ out) {
    const int tid = threadIdx.x;
    const int lane = tid & 31;

    __shared__ int s_items[QPB];
    __shared__ int s_cnt;
    __shared__ int s_head;
    __shared__ unsigned long long s_acc;
    if (tid == 0) { s_cnt = 0; s_head = 0; s_acc = 0ULL; }
    __syncthreads();

    // cull: q = blockIdx.x + tid * PGRID (strided -> even diagonal spread)
    unsigned int q = blockIdx.x + (unsigned int)tid * PGRID;
    if (tid < QPB && q < TOTQ) {
        int chain = (q >= NSUBP) ? 1 : 0;
        int p = (int)q - chain * NSUBP;
        // triangular decode over N=272: S(ci) = ci*(545-ci)/2
        float disc = 297025.0f - 8.0f * (float)p;     // 545^2 - 8p (exact fp32)
        int ci = (int)((545.0f - sqrtf(disc)) * 0.5f);
        if (ci < 0) ci = 0;
        if (ci > NSUB - 1) ci = NSUB - 1;
        while (ci > 0 && (ci * (545 - ci)) / 2 > p) ci--;
        while (((ci + 1) * (544 - ci)) / 2 <= p) ci++;
        int cj = ci + (p - (ci * (545 - ci)) / 2);

        float4 bi = g_cb32[chain][ci];
        float4 bj = g_cb32[chain][cj];
        float dx = bi.x - bj.x, dy = bi.y - bj.y, dz = bi.z - bj.z;
        float rr = bi.w + bj.w + DCUT_HAT;
        if (dx * dx + dy * dy + dz * dz <= rr * rr) {
            int idx = atomicAdd(&s_cnt, 1);
            s_items[idx] = (chain << 20) | (ci << 10) | cj;
        }
    }
    __syncthreads();

    const int n = s_cnt;
    // dynamic item pop: warps steal from shared counter
    for (;;) {
        int idx;
        if (lane == 0) idx = atomicAdd(&s_head, 1);
        idx = __shfl_sync(0xffffffffu, idx, 0);
        if (idx >= n) break;

        const int item = s_items[idx];
        const int chain = item >> 20;
        const int ci = (item >> 10) & 1023;
        const int cj = item & 1023;
        const float4* jp = &g_pts[chain][cj * 32];
        float4 ip = g_pts[chain][ci * 32 + lane];

        float acc = (ci == cj) ? tile32<true>(jp, ip, lane)
                               : tile32<false>(jp, ip, lane);
        // per-item warp reduce + quantize (order-independent integer sum)
        #pragma unroll
        for (int d = 16; d > 0; d >>= 1)
            acc += __shfl_down_sync(0xffffffffu, acc, d);
        if (lane == 0)
            atomicAdd(&s_acc, (unsigned long long)__float2ll_rn(acc * FXSCALE));
    }
    __syncthreads();

    if (tid == 0) {
        if (s_acc) atomicAdd(&g_acc, s_acc);
        __threadfence();
        unsigned int done = atomicAdd(&g_count, 1u);
        if (done == PGRID - 1) {
            unsigned long long raw = atomicAdd(&g_acc, 0ULL);
            double sum = (double)(long long)raw * (1.0 / (double)FXSCALE);
            out[0] = (float)(10.0 * (2.0 * sum + (double)(NCHAIN * NPTS)));
            // reset for next graph replay
            atomicExch(&g_acc, 0ULL);
            atomicExch(&g_count, 0u);
        }
    }
}

extern "C" void kernel_launch(void* const* d_in, const int* in_sizes, int n_in,
                              void* d_out, int out_size) {
    const float* conf = (const float*)d_in[0];
    float* out = (float*)d_out;

    setup_kernel<<<NCHAIN, 1024>>>(conf);
    pair_kernel<<<PGRID, PBLOCK>>>(out);
}

// round 16
// speedup vs baseline: 1.8587x; 1.0652x over previous
#include <cuda_runtime.h>

// Problem constants
#define NPTS     8193            // positions per chain (incl. leading zero row)
#define NCHAIN   2
#define CONFLEN  16388

// 32-point sub-chunks, pair space culled lane-parallel in the pair kernel
#define NSUB     272                             // PADN / 32
#define PADN     (NSUB * 32)                     // 8704
#define NSUBP    (NSUB * (NSUB + 1) / 2)         // 37128 fine pairs per chain
#define TOTQ     (NSUBP * NCHAIN)                // 74256

#define PBLOCK   256
#define PGRID    888                             // 6 blocks/SM
#define QPB      ((TOTQ + PGRID - 1) / PGRID)    // 84 q's per block

// Scaled-space cutoff: dropped pair value <= 2^(-0.5*64) = 2.3e-10
#define DCUT_HAT 8.0f

// Fixed-point scale for deterministic integer accumulation
#define FXSCALE  16777216.0f     // 2^24

// Scratch (no allocations allowed; zero-initialized at load)
__device__ float4 g_pts[NCHAIN][PADN];           // (x_hat, y_hat, z_hat, a)
__device__ float4 g_cb32[NCHAIN][NSUB];          // fine bounds (cx,cy,cz,r)
__device__ unsigned long long g_acc;             // fixed-point sum
__device__ unsigned int g_count;                 // finished-block counter

// ---------------------------------------------------------------------------
// Setup: one block (1024 threads) per chain, 8 steps/thread register-resident
// prefix sum; emits scaled points, pads, and 32-point sub-chunk bounds.
// ---------------------------------------------------------------------------
__global__ void __launch_bounds__(1024)
setup_kernel(const float* __restrict__ conf) {
    const int chain = blockIdx.x;
    const int t = threadIdx.x;
    const int lane = t & 31, warp = t >> 5;
    const float2* cp = (const float2*)(conf + chain * CONFLEN + 4);
    const float TWO_PI = 6.2831853071795864769f;

    float px[8], py[8], pz[8];
    float sx = 0.f, sy = 0.f, sz = 0.f;
    #pragma unroll
    for (int m = 0; m < 8; m++) {
        float2 rr = cp[t * 8 + m];
        float r1 = rr.x + 0.5f;
        float r2 = rr.y + 0.5f;
        float z  = 1.0f - 2.0f * r2;                   // cos(theta)
        float sth = sqrtf(fmaxf(1.0f - z * z, 0.0f));  // sin(theta)
        float s, c;
        __sincosf(r1 * TWO_PI, &s, &c);
        sx += sth * c;
        sy += sth * s;
        sz += z;
        px[m] = sx; py[m] = sy; pz[m] = sz;
    }

    // warp inclusive scan of thread totals
    float tx = sx, ty = sy, tz = sz;
    #pragma unroll
    for (int d = 1; d < 32; d <<= 1) {
        float ox = __shfl_up_sync(0xffffffffu, tx, d);
        float oy = __shfl_up_sync(0xffffffffu, ty, d);
        float oz = __shfl_up_sync(0xffffffffu, tz, d);
        if (lane >= d) { tx += ox; ty += oy; tz += oz; }
    }

    __shared__ float3 wtot[32], woff[32];
    __shared__ float4 lastpt_s;
    if (lane == 31) wtot[warp] = make_float3(tx, ty, tz);
    __syncthreads();
    if (t == 0) {
        float ax = 0.f, ay = 0.f, az = 0.f;
        #pragma unroll
        for (int w = 0; w < 32; w++) {
            float3 v = wtot[w];
            woff[w] = make_float3(ax, ay, az);
            ax += v.x; ay += v.y; az += v.z;
        }
    }
    __syncthreads();
    float bx = woff[warp].x + (tx - sx);
    float by = woff[warp].y + (ty - sy);
    float bz = woff[warp].z + (tz - sz);

    // arg = a_i + a_j + dot(p_hat_i, p_hat_j), p_hat = SS*p, a=-0.5|p_hat|^2
    const float S2 = 8.0f * 1.4426950408889634f;   // 8*log2(e)
    const float SS = sqrtf(S2);                    // scaled step length

    float4 mylast = make_float4(0.f, 0.f, 0.f, 0.f);
    float mnx = 1e30f, mxx = -1e30f, mny = 1e30f, mxy = -1e30f;
    float mnz = 1e30f, mxz = -1e30f;
    #pragma unroll
    for (int m = 0; m < 8; m++) {
        float xh = SS * (bx + px[m]);
        float yh = SS * (by + py[m]);
        float zh = SS * (bz + pz[m]);
        float a = -0.5f * (xh * xh + yh * yh + zh * zh);
        mylast = make_float4(xh, yh, zh, a);
        g_pts[chain][t * 8 + m + 1] = mylast;
        mnx = fminf(mnx, xh); mxx = fmaxf(mxx, xh);
        mny = fminf(mny, yh); mxy = fmaxf(mxy, yh);
        mnz = fminf(mnz, zh); mxz = fmaxf(mxz, zh);
    }
    if (t == 0)    g_pts[chain][0] = make_float4(0.f, 0.f, 0.f, 0.f);
    if (t == 1023) lastpt_s = mylast;   // point 8192

    // fine bounds: threads 4c..4c+3 cover points [32c+1, 32c+33);
    // +SS inflation covers the left boundary point 32c.
    #pragma unroll
    for (int d = 1; d < 4; d <<= 1) {
        mnx = fminf(mnx, __shfl_xor_sync(0xffffffffu, mnx, d, 4));
        mxx = fmaxf(mxx, __shfl_xor_sync(0xffffffffu, mxx, d, 4));
        mny = fminf(mny, __shfl_xor_sync(0xffffffffu, mny, d, 4));
        mxy = fmaxf(mxy, __shfl_xor_sync(0xffffffffu, mxy, d, 4));
        mnz = fminf(mnz, __shfl_xor_sync(0xffffffffu, mnz, d, 4));
        mxz = fmaxf(mxz, __shfl_xor_sync(0xffffffffu, mxz, d, 4));
    }
    if ((t & 3) == 0) {
        float hx = 0.5f * (mxx - mnx), hy = 0.5f * (mxy - mny), hz = 0.5f * (mxz - mnz);
        float r = sqrtf(hx * hx + hy * hy + hz * hz) + SS + 1e-2f;
        g_cb32[chain][t >> 2] = make_float4(0.5f * (mnx + mxx), 0.5f * (mny + mxy),
                                            0.5f * (mnz + mxz), r);
    }
    __syncthreads();

    // pads at lastpt with a=-1e30 (exp2 underflows to exactly 0)
    if (t < PADN - NPTS)
        g_pts[chain][NPTS + t] =
            make_float4(lastpt_s.x, lastpt_s.y, lastpt_s.z, -1e30f);

    // sub-chunk 256 holds real point 8192 + pads at lastpt; 257..271 pure pads
    if (t == 0)
        g_cb32[chain][256] = make_float4(lastpt_s.x, lastpt_s.y, lastpt_s.z, 0.05f);
    if (t >= 4 && t <= 18)
        g_cb32[chain][256 + t - 3] = make_float4(2e15f, 2e15f, 2e15f, 0.f);
}

// ---------------------------------------------------------------------------
// Masked 32x32 sub-tile: each lane owns j=lane (ONE coalesced load), tests
// its j against the i-tile bounding sphere (tighter than tile-tile test),
// then the warp walks only live j's, broadcasting via shfl (2 per iter).
// Returns this lane's partial (no reduction here).
// ---------------------------------------------------------------------------
template <bool DIAG>
__device__ __forceinline__ float tile32m(const float4* __restrict__ jp,
                                         float4 ip, int lane, float4 bi) {
    float4 q = __ldg(&jp[lane]);     // lane owns j = lane
    float dx = q.x - bi.x, dy = q.y - bi.y, dz = q.z - bi.z;
    float rl = bi.w + DCUT_HAT;
    bool jlive = (dx * dx + dy * dy + dz * dz) <= rl * rl;
    unsigned int jmask = __ballot_sync(0xffffffffu, jlive);

    float a0 = 0.f, a1 = 0.f;
    while (jmask) {
        int b0 = __ffs(jmask) - 1;
        jmask &= jmask - 1;
        int b1 = jmask ? (__ffs(jmask) - 1) : -1;
        if (b1 >= 0) jmask &= jmask - 1;

        float qx0 = __shfl_sync(0xffffffffu, q.x, b0);
        float qy0 = __shfl_sync(0xffffffffu, q.y, b0);
        float qz0 = __shfl_sync(0xffffffffu, q.z, b0);
        float qw0 = __shfl_sync(0xffffffffu, q.w, b0);
        float m0 = fmaf(ip.x, qx0, qw0);
        m0 = fmaf(ip.y, qy0, m0);
        m0 = fmaf(ip.z, qz0, m0);
        float e0;
        asm("ex2.approx.f32 %0, %1;" : "=f"(e0) : "f"(m0 + ip.w));
        a0 += (!DIAG || b0 > lane) ? e0 : 0.f;

        if (b1 >= 0) {
            float qx1 = __shfl_sync(0xffffffffu, q.x, b1);
            float qy1 = __shfl_sync(0xffffffffu, q.y, b1);
            float qz1 = __shfl_sync(0xffffffffu, q.z, b1);
            float qw1 = __shfl_sync(0xffffffffu, q.w, b1);
            float m1 = fmaf(ip.x, qx1, qw1);
            m1 = fmaf(ip.y, qy1, m1);
            m1 = fmaf(ip.z, qz1, m1);
            float e1;
            asm("ex2.approx.f32 %0, %1;" : "=f"(e1) : "f"(m1 + ip.w));
            a1 += (!DIAG || b1 > lane) ? e1 : 0.f;
        }
    }
    return a0 + a1;
}

// ---------------------------------------------------------------------------
// Pair kernel: 888 blocks x 256. Block culls its 84 statically-assigned
// q-indices (1/thread) into a SHARED live list; the block's 8 warps then POP
// items dynamically (shared counter). Each tile is warp-reduced and quantized
// to fixed point PER ITEM (order-independent), accumulated in a shared u64;
// one global atomic per block. Last block finalizes + resets.
// ---------------------------------------------------------------------------
__global__ void __launch_bounds__(PBLOCK)
pair_kernel(float* __restrict__ out) {
    const int tid = threadIdx.x;
    const int lane = tid & 31;

    __shared__ int s_items[QPB];
    __shared__ int s_cnt;
    __shared__ int s_head;
    __shared__ unsigned long long s_acc;
    if (tid == 0) { s_cnt = 0; s_head = 0; s_acc = 0ULL; }
    __syncthreads();

    // cull: q = blockIdx.x + tid * PGRID (strided -> even diagonal spread)
    unsigned int q = blockIdx.x + (unsigned int)tid * PGRID;
    if (tid < QPB && q < TOTQ) {
        int chain = (q >= NSUBP) ? 1 : 0;
        int p = (int)q - chain * NSUBP;
        // triangular decode over N=272: S(ci) = ci*(545-ci)/2
        float disc = 297025.0f - 8.0f * (float)p;     // 545^2 - 8p (exact fp32)
        int ci = (int)((545.0f - sqrtf(disc)) * 0.5f);
        if (ci < 0) ci = 0;
        if (ci > NSUB - 1) ci = NSUB - 1;
        while (ci > 0 && (ci * (545 - ci)) / 2 > p) ci--;
        while (((ci + 1) * (544 - ci)) / 2 <= p) ci++;
        int cj = ci + (p - (ci * (545 - ci)) / 2);

        float4 bi = g_cb32[chain][ci];
        float4 bj = g_cb32[chain][cj];
        float dx = bi.x - bj.x, dy = bi.y - bj.y, dz = bi.z - bj.z;
        float rr = bi.w + bj.w + DCUT_HAT;
        if (dx * dx + dy * dy + dz * dz <= rr * rr) {
            int idx = atomicAdd(&s_cnt, 1);
            s_items[idx] = (chain << 20) | (ci << 10) | cj;
        }
    }
    __syncthreads();

    const int n = s_cnt;
    // dynamic item pop: warps steal from shared counter
    for (;;) {
        int idx;
        if (lane == 0) idx = atomicAdd(&s_head, 1);
        idx = __shfl_sync(0xffffffffu, idx, 0);
        if (idx >= n) break;

        const int item = s_items[idx];
        const int chain = item >> 20;
        const int ci = (item >> 10) & 1023;
        const int cj = item & 1023;
        const float4* jp = &g_pts[chain][cj * 32];
        float4 ip = g_pts[chain][ci * 32 + lane];
        float4 bi = __ldg(&g_cb32[chain][ci]);   // i-tile ball for per-j cull

        float acc = (ci == cj) ? tile32m<true>(jp, ip, lane, bi)
                               : tile32m<false>(jp, ip, lane, bi);
        // per-item warp reduce + quantize (order-independent integer sum)
        #pragma unroll
        for (int d = 16; d > 0; d >>= 1)
            acc += __shfl_down_sync(0xffffffffu, acc, d);
        if (lane == 0)
            atomicAdd(&s_acc, (unsigned long long)__float2ll_rn(acc * FXSCALE));
    }
    __syncthreads();

    if (tid == 0) {
        if (s_acc) atomicAdd(&g_acc, s_acc);
        __threadfence();
        unsigned int done = atomicAdd(&g_count, 1u);
        if (done == PGRID - 1) {
            unsigned long long raw = atomicAdd(&g_acc, 0ULL);
            double sum = (double)(long long)raw * (1.0 / (double)FXSCALE);
            out[0] = (float)(10.0 * (2.0 * sum + (double)(NCHAIN * NPTS)));
            // reset for next graph replay
            atomicExch(&g_acc, 0ULL);
            atomicExch(&g_count, 0u);
        }
    }
}

extern "C" void kernel_launch(void* const* d_in, const int* in_sizes, int n_in,
                              void* d_out, int out_size) {
    const float* conf = (const float*)d_in[0];
    float* out = (float*)d_out;

    setup_kernel<<<NCHAIN, 1024>>>(conf);
    pair_kernel<<<PGRID, PBLOCK>>>(out);
}